// round 9
// baseline (speedup 1.0000x reference)
#include <cuda_runtime.h>
#include <cuda_fp16.h>
#include <cuda_bf16.h>
#include <cstdint>

#define HDIM 128
#define MAXN 50000
#define MAXE 600000
#define MAXG 128
#define CDIM 10

// ---------------- scratch (no allocations allowed) ----------------
__device__ int      g_is64;
__device__ int      g_cnt[MAXN];
__device__ float    g_dinv[MAXN];
__device__ int      g_ptr[MAXN + 1];
__device__ int      g_pos[MAXN];
__device__ int      g_csrc[MAXE];
__device__ int      g_bsum[128];
__device__ float    g_h[(size_t)MAXN * HDIM];
__device__ __half   g_tA[(size_t)MAXN * HDIM];
__device__ __half   g_tB[(size_t)MAXN * HDIM];
__device__ float    g_pool[MAXG * HDIM];
__device__ float    g_gcnt[MAXG];
__device__ uint32_t g_wth[3][HDIM * 64];   // W^T bf16-hi, packed k-pairs: [n][kp]
__device__ uint32_t g_wtl[3][HDIM * 64];   // W^T bf16-lo

__device__ __forceinline__ int loadIdx(const void* p, long long i, int is64) {
    if (is64) return (int)((const long long*)p)[i];
    return ((const int*)p)[i];
}

// ---------------- fused prep ----------------
__global__ void k_init(const void* ei, int n, int g) {
    int i = blockIdx.x * blockDim.x + threadIdx.x;
    if (i == 0) {
        const int* w = (const int*)ei;
        int all0 = 1;
        for (int j = 0; j < 32; j++) if (w[2 * j + 1] != 0) all0 = 0;
        g_is64 = all0;
    }
    if (i < n) g_cnt[i] = 0;
    if (i < g * HDIM) g_pool[i] = 0.f;
    if (i < g) g_gcnt[i] = 0.f;
}

__global__ void k_deg(const void* ei, int E) {
    int e = blockIdx.x * blockDim.x + threadIdx.x;
    if (e >= E) return;
    int d = loadIdx(ei, (long long)E + e, g_is64);
    atomicAdd(&g_cnt[d], 1);
}

__global__ void k_scan1(int n) {
    __shared__ int s[1024];
    int tid = threadIdx.x;
    int i = blockIdx.x * 1024 + tid;
    int v = (i < n) ? g_cnt[i] : 0;
    if (i < n) g_dinv[i] = rsqrtf((float)(v + 1));   // +1 = self-loop
    s[tid] = v;
    __syncthreads();
    for (int off = 1; off < 1024; off <<= 1) {
        int t = (tid >= off) ? s[tid - off] : 0;
        __syncthreads();
        s[tid] += t;
        __syncthreads();
    }
    if (i < n) g_ptr[i] = s[tid] - v;
    if (tid == 1023) g_bsum[blockIdx.x] = s[tid];
}

__global__ void k_scan23(int n, int nb) {
    __shared__ int carry;
    if (threadIdx.x == 0) {
        int acc = 0;
        for (int b = 0; b < blockIdx.x; b++) acc += g_bsum[b];
        carry = acc;
        if (blockIdx.x == nb - 1) g_ptr[n] = acc + g_bsum[nb - 1];
    }
    __syncthreads();
    int i = blockIdx.x * 1024 + threadIdx.x;
    if (i < n) {
        int p = g_ptr[i] + carry;
        g_ptr[i] = p;
        g_pos[i] = p;
    }
}

__global__ void k_fill(const void* ei, const void* batch, int E, int n) {
    int e = blockIdx.x * blockDim.x + threadIdx.x;
    if (e >= E) return;
    int is64 = g_is64;
    int s = loadIdx(ei, e, is64);
    int d = loadIdx(ei, (long long)E + e, is64);
    int p = atomicAdd(&g_pos[d], 1);
    g_csrc[p] = s;
    if (e < n) {
        int g = loadIdx(batch, e, is64);
        atomicAdd(&g_gcnt[g], 1.0f);
    }
}

// ---------------- W split/transpose ----------------
__global__ void k_wsplit(const float* __restrict__ W1, const float* __restrict__ W2,
                         const float* __restrict__ W3) {
    int i = blockIdx.x * blockDim.x + threadIdx.x;
    if (i >= 3 * HDIM * 64) return;
    int l = i >> 13, r = i & 8191;
    int n = r >> 6, kp = r & 63;
    const float* W = (l == 0) ? W1 : ((l == 1) ? W2 : W3);
    float a = W[(2 * kp) * HDIM + n];
    float b = W[(2 * kp + 1) * HDIM + n];
    float ah = __bfloat162float(__float2bfloat16_rn(a));
    float bh = __bfloat162float(__float2bfloat16_rn(b));
    __nv_bfloat162 hp = __floats2bfloat162_rn(a, b);
    __nv_bfloat162 lp = __floats2bfloat162_rn(a - ah, b - bh);
    g_wth[l][n * 64 + kp] = *(uint32_t*)&hp;
    g_wtl[l][n * 64 + kp] = *(uint32_t*)&lp;
}

// ---------------- HMMA helper ----------------
__device__ __forceinline__ void mma_bf16(float* c, const uint32_t* a, uint32_t b0, uint32_t b1) {
    asm volatile("mma.sync.aligned.m16n8k16.row.col.f32.bf16.bf16.f32 "
                 "{%0,%1,%2,%3}, {%4,%5,%6,%7}, {%8,%9}, {%0,%1,%2,%3};"
                 : "+f"(c[0]), "+f"(c[1]), "+f"(c[2]), "+f"(c[3])
                 : "r"(a[0]), "r"(a[1]), "r"(a[2]), "r"(a[3]), "r"(b0), "r"(b1));
}

// smem layout (u32 units): M=64 A tile + full B, stride 68
#define SROW 68
#define SA_HI 0
#define SA_LO (64 * SROW)
#define SB_HI (2 * 64 * SROW)
#define SB_LO (SB_HI + 128 * SROW)
#define GSMEM_BYTES ((SB_LO + 128 * SROW) * 4)

// shared MMA phase: computes C[64 x 128] = A @ B^T from split smem, writes fp16 dst
__device__ __forceinline__ void mma_phase(const uint32_t* sm, __half* dst,
                                          int rowbase, int nrows, int tid) {
    int lane = tid & 31, warp = tid >> 5;
    int g = lane >> 2, tig = lane & 3;
    int m0 = (warp >> 1) * 16;
    int n0 = (warp & 1) * 64;

    float acc[8][4];
#pragma unroll
    for (int j = 0; j < 8; j++)
#pragma unroll
        for (int q = 0; q < 4; q++) acc[j][q] = 0.f;

#pragma unroll 1
    for (int s = 0; s < 8; s++) {
        int kb = s * 8;
        int o0 = (m0 + g) * SROW + kb + tig;
        int o1 = (m0 + 8 + g) * SROW + kb + tig;
        uint32_t ah[4], al[4];
        ah[0] = sm[SA_HI + o0]; ah[1] = sm[SA_HI + o1];
        ah[2] = sm[SA_HI + o0 + 4]; ah[3] = sm[SA_HI + o1 + 4];
        al[0] = sm[SA_LO + o0]; al[1] = sm[SA_LO + o1];
        al[2] = sm[SA_LO + o0 + 4]; al[3] = sm[SA_LO + o1 + 4];
#pragma unroll
        for (int j = 0; j < 8; j++) {
            int nn = n0 + j * 8 + g;
            int ob = nn * SROW + kb + tig;
            uint32_t bh0 = sm[SB_HI + ob], bh1 = sm[SB_HI + ob + 4];
            uint32_t bl0 = sm[SB_LO + ob], bl1 = sm[SB_LO + ob + 4];
            mma_bf16(acc[j], ah, bh0, bh1);
            mma_bf16(acc[j], ah, bl0, bl1);
            mma_bf16(acc[j], al, bh0, bh1);
        }
    }

#pragma unroll
    for (int j = 0; j < 8; j++) {
        int r0 = rowbase + m0 + g;
        int c = n0 + j * 8 + tig * 2;
        if (r0 < nrows) {
            __half2 h = __floats2half2_rn(acc[j][0], acc[j][1]);
            *(__half2*)&dst[(size_t)r0 * HDIM + c] = h;
        }
        if (r0 + 8 < nrows) {
            __half2 h = __floats2half2_rn(acc[j][2], acc[j][3]);
            *(__half2*)&dst[(size_t)(r0 + 8) * HDIM + c] = h;
        }
    }
}

// B copy: pre-split W^T global -> smem
__device__ __forceinline__ void b_copy(uint32_t* sm, int layer, int tid) {
    const uint32_t* wth = g_wth[layer];
    const uint32_t* wtl = g_wtl[layer];
#pragma unroll
    for (int it = 0; it < 32; it++) {
        int idx = tid + it * 256;           // 0..8191
        int n = idx >> 6, kp = idx & 63;
        sm[SB_HI + n * SROW + kp] = wth[idx];
        sm[SB_LO + n * SROW + kp] = wtl[idx];
    }
}

// split a float pair to bf16 hi/lo u32s
__device__ __forceinline__ void split2(float x, float y, uint32_t& hi, uint32_t& lo) {
    float xh = __bfloat162float(__float2bfloat16_rn(x));
    float yh = __bfloat162float(__float2bfloat16_rn(y));
    __nv_bfloat162 hp = __floats2bfloat162_rn(x, y);
    __nv_bfloat162 lp = __floats2bfloat162_rn(x - xh, y - yh);
    hi = *(uint32_t*)&hp;
    lo = *(uint32_t*)&lp;
}

// ---------------- GEMM1: dst = x @ W1 (A loaded fp32 from external) ----------------
__global__ __launch_bounds__(256, 2) void k_gemm1(const float* __restrict__ A,
                                                  __half* __restrict__ dst, int nrows) {
    extern __shared__ uint32_t sm[];
    int tid = threadIdx.x;
    int rowbase = blockIdx.x * 64;

    b_copy(sm, 0, tid);
#pragma unroll
    for (int it = 0; it < 16; it++) {
        int idx = tid + it * 256;           // 0..4095
        int row = idx >> 6, kp = idx & 63;
        int r = min(rowbase + row, nrows - 1);
        float2 v = *(const float2*)&A[(size_t)r * HDIM + kp * 2];
        uint32_t hi, lo;
        split2(v.x, v.y, hi, lo);
        sm[SA_HI + row * SROW + kp] = hi;
        sm[SA_LO + row * SROW + kp] = lo;
    }
    __syncthreads();
    mma_phase(sm, dst, rowbase, nrows, tid);
}

// ---------------- fused agg+GEMM: h = relu(Ahat*src + b); dst = h @ W_layer ----------------
__global__ __launch_bounds__(256, 2) void k_agg_gemm(const __half* __restrict__ src,
                                                     __half* __restrict__ dst,
                                                     const float* __restrict__ bias,
                                                     int layer, int n, int nrows) {
    extern __shared__ uint32_t sm[];
    int tid = threadIdx.x;
    int warp = tid >> 5, lane = tid & 31;
    int rowbase = blockIdx.x * 64;

    b_copy(sm, layer, tid);

    float4 b = ((const float4*)bias)[lane];
#pragma unroll 1
    for (int rr = 0; rr < 8; rr++) {
        int row = warp * 8 + rr;
        int node = rowbase + row;
        float4 r = make_float4(0.f, 0.f, 0.f, 0.f);
        if (node < n) {
            float4 acc = make_float4(0.f, 0.f, 0.f, 0.f);
            int beg = g_ptr[node], end = g_ptr[node + 1];
#pragma unroll 4
            for (int p = beg; p < end; p++) {
                int s = g_csrc[p];
                float ds = g_dinv[s];
                uint2 raw = *(const uint2*)&src[(size_t)s * HDIM + lane * 4];
                float2 v0 = __half22float2(*(__half2*)&raw.x);
                float2 v1 = __half22float2(*(__half2*)&raw.y);
                acc.x += ds * v0.x; acc.y += ds * v0.y;
                acc.z += ds * v1.x; acc.w += ds * v1.y;
            }
            float di = g_dinv[node];
            float di2 = di * di;
            uint2 sraw = *(const uint2*)&src[(size_t)node * HDIM + lane * 4];
            float2 s0 = __half22float2(*(__half2*)&sraw.x);
            float2 s1 = __half22float2(*(__half2*)&sraw.y);
            r.x = fmaxf(di * acc.x + di2 * s0.x + b.x, 0.f);
            r.y = fmaxf(di * acc.y + di2 * s0.y + b.y, 0.f);
            r.z = fmaxf(di * acc.z + di2 * s1.x + b.z, 0.f);
            r.w = fmaxf(di * acc.w + di2 * s1.y + b.w, 0.f);
        }
        uint32_t hi0, lo0, hi1, lo1;
        split2(r.x, r.y, hi0, lo0);
        split2(r.z, r.w, hi1, lo1);
        int o = row * SROW + lane * 2;
        sm[SA_HI + o] = hi0; sm[SA_HI + o + 1] = hi1;
        sm[SA_LO + o] = lo0; sm[SA_LO + o + 1] = lo1;
    }
    __syncthreads();
    mma_phase(sm, dst, rowbase, nrows, tid);
}

// ---------------- final aggregation -> g_h (fp32, for pooling) ----------------
__global__ __launch_bounds__(256) void k_agg(const __half* __restrict__ src,
                                             const float* __restrict__ bias, int n) {
    int warp = threadIdx.x >> 5, lane = threadIdx.x & 31;
    int node = blockIdx.x * 8 + warp;
    if (node >= n) return;
    float4 acc = make_float4(0.f, 0.f, 0.f, 0.f);
    int beg = g_ptr[node], end = g_ptr[node + 1];
#pragma unroll 4
    for (int p = beg; p < end; p++) {
        int s = g_csrc[p];
        float ds = g_dinv[s];
        uint2 raw = *(const uint2*)&src[(size_t)s * HDIM + lane * 4];
        float2 v0 = __half22float2(*(__half2*)&raw.x);
        float2 v1 = __half22float2(*(__half2*)&raw.y);
        acc.x += ds * v0.x; acc.y += ds * v0.y;
        acc.z += ds * v1.x; acc.w += ds * v1.y;
    }
    float di = g_dinv[node];
    float di2 = di * di;
    uint2 sraw = *(const uint2*)&src[(size_t)node * HDIM + lane * 4];
    float2 s0 = __half22float2(*(__half2*)&sraw.x);
    float2 s1 = __half22float2(*(__half2*)&sraw.y);
    float4 b = ((const float4*)bias)[lane];
    float4 r;
    r.x = fmaxf(di * acc.x + di2 * s0.x + b.x, 0.f);
    r.y = fmaxf(di * acc.y + di2 * s0.y + b.y, 0.f);
    r.z = fmaxf(di * acc.z + di2 * s1.x + b.z, 0.f);
    r.w = fmaxf(di * acc.w + di2 * s1.y + b.w, 0.f);
    ((float4*)g_h)[(size_t)node * 32 + lane] = r;
}

// ---------------- pooling ----------------
#define PCHUNK 64
__global__ __launch_bounds__(128) void k_pool(const void* batch, int n) {
    int f = threadIdx.x;
    int n0 = blockIdx.x * PCHUNK;
    int n1 = min(n0 + PCHUNK, n);
    if (n0 >= n) return;
    int is64 = g_is64;
    int curg = loadIdx(batch, n0, is64);
    float acc = 0.f;
    for (int i = n0; i < n1; i++) {
        int g = loadIdx(batch, i, is64);
        if (g != curg) {
            atomicAdd(&g_pool[curg * HDIM + f], acc);
            acc = 0.f; curg = g;
        }
        acc += g_h[(size_t)i * HDIM + f];
    }
    atomicAdd(&g_pool[curg * HDIM + f], acc);
}

// ---------------- classifier ----------------
__global__ void k_cls(const float* __restrict__ Wl, const float* __restrict__ bl,
                      float* __restrict__ out) {
    int g = blockIdx.x;
    int lane = threadIdx.x;
    float invc = 1.0f / fmaxf(g_gcnt[g], 1.0f);
    float acc = (lane < CDIM) ? bl[lane] : 0.f;
    for (int k = 0; k < HDIM; k++) {
        float p = g_pool[g * HDIM + k] * invc;
        if (lane < CDIM) acc += p * Wl[k * CDIM + lane];
    }
    if (lane < CDIM) out[g * CDIM + lane] = acc;
}

// ---------------- launch ----------------
extern "C" void kernel_launch(void* const* d_in, const int* in_sizes, int n_in,
                              void* d_out, int out_size) {
    const float* x  = (const float*)d_in[0];
    const float* W1 = (const float*)d_in[1];
    const float* b1 = (const float*)d_in[2];
    const float* W2 = (const float*)d_in[3];
    const float* b2 = (const float*)d_in[4];
    const float* W3 = (const float*)d_in[5];
    const float* b3 = (const float*)d_in[6];
    const float* Wl = (const float*)d_in[7];
    const float* bl = (const float*)d_in[8];
    const void*  ei = d_in[9];
    const void*  bt = d_in[10];

    int N = in_sizes[0] / HDIM;
    int E = in_sizes[9] / 2;
    int G = out_size / CDIM;

    static cudaStream_t s_side = nullptr;
    static cudaEvent_t ev_fork = nullptr, ev_join = nullptr;
    if (!s_side) {
        cudaStreamCreateWithFlags(&s_side, cudaStreamNonBlocking);
        cudaEventCreateWithFlags(&ev_fork, cudaEventDisableTiming);
        cudaEventCreateWithFlags(&ev_join, cudaEventDisableTiming);
        cudaFuncSetAttribute(k_gemm1, cudaFuncAttributeMaxDynamicSharedMemorySize, GSMEM_BYTES);
        cudaFuncSetAttribute(k_agg_gemm, cudaFuncAttributeMaxDynamicSharedMemorySize, GSMEM_BYTES);
    }

    // device-global pointers for the half buffers
    static __half *p_tA = nullptr, *p_tB = nullptr;
    if (!p_tA) {
        cudaGetSymbolAddress((void**)&p_tA, g_tA);
        cudaGetSymbolAddress((void**)&p_tB, g_tB);
    }

    int nb = (N + 1023) / 1024;
    int mma_blocks = (N + 63) / 64;
    int agg_blocks = (N + 7) / 8;

    // fork: CSR prep on side stream; W split + GEMM1 on main
    cudaEventRecord(ev_fork, 0);
    cudaStreamWaitEvent(s_side, ev_fork, 0);

    k_init<<<(N + 255) / 256, 256, 0, s_side>>>(ei, N, G);
    k_deg<<<(E + 255) / 256, 256, 0, s_side>>>(ei, E);
    k_scan1<<<nb, 1024, 0, s_side>>>(N);
    k_scan23<<<nb, 1024, 0, s_side>>>(N, nb);
    k_fill<<<(E + 255) / 256, 256, 0, s_side>>>(ei, bt, E, N);
    cudaEventRecord(ev_join, s_side);

    k_wsplit<<<(3 * HDIM * 64 + 255) / 256, 256>>>(W1, W2, W3);
    k_gemm1<<<mma_blocks, 256, GSMEM_BYTES>>>(x, p_tA, N);

    cudaStreamWaitEvent(0, ev_join, 0);

    k_agg_gemm<<<mma_blocks, 256, GSMEM_BYTES>>>(p_tA, p_tB, b1, 1, N, N);
    k_agg_gemm<<<mma_blocks, 256, GSMEM_BYTES>>>(p_tB, p_tA, b2, 2, N, N);
    k_agg<<<agg_blocks, 256>>>(p_tA, b3, N);

    k_pool<<<(N + PCHUNK - 1) / PCHUNK, 128>>>(bt, N);
    k_cls<<<G, 32>>>(Wl, bl, (float*)d_out);
}

// round 10
// speedup vs baseline: 1.2859x; 1.2859x over previous
#include <cuda_runtime.h>
#include <cuda_fp16.h>
#include <cuda_bf16.h>
#include <cstdint>

#define HDIM 128
#define MAXN 50000
#define MAXE 600000
#define MAXG 128
#define CDIM 10

// ---------------- scratch (no allocations allowed) ----------------
__device__ int      g_is64;
__device__ int      g_cnt[MAXN];
__device__ float    g_dinv[MAXN];
__device__ int      g_ptr[MAXN + 1];
__device__ int      g_pos[MAXN];
__device__ int      g_csrc[MAXE];
__device__ int      g_bsum[128];
__device__ float    g_h[(size_t)MAXN * HDIM];
__device__ __half   g_tmp[(size_t)MAXN * HDIM];
__device__ float    g_pool[MAXG * HDIM];
__device__ float    g_gcnt[MAXG];
__device__ uint32_t g_wth[3][HDIM * 64];   // W^T bf16-hi, packed k-pairs: [n][kp]
__device__ uint32_t g_wtl[3][HDIM * 64];   // W^T bf16-lo

__device__ __forceinline__ int loadIdx(const void* p, long long i, int is64) {
    if (is64) return (int)((const long long*)p)[i];
    return ((const int*)p)[i];
}

// ---------------- fused prep ----------------
__global__ void k_init(const void* ei, int n, int g) {
    int i = blockIdx.x * blockDim.x + threadIdx.x;
    if (i == 0) {
        const int* w = (const int*)ei;
        int all0 = 1;
        for (int j = 0; j < 32; j++) if (w[2 * j + 1] != 0) all0 = 0;
        g_is64 = all0;
    }
    if (i < n) g_cnt[i] = 0;
    if (i < g * HDIM) g_pool[i] = 0.f;
    if (i < g) g_gcnt[i] = 0.f;
}

__global__ void k_deg(const void* ei, int E) {
    int e = blockIdx.x * blockDim.x + threadIdx.x;
    if (e >= E) return;
    int d = loadIdx(ei, (long long)E + e, g_is64);
    atomicAdd(&g_cnt[d], 1);
}

__global__ void k_scan1(int n) {
    __shared__ int s[1024];
    int tid = threadIdx.x;
    int i = blockIdx.x * 1024 + tid;
    int v = (i < n) ? g_cnt[i] : 0;
    if (i < n) g_dinv[i] = rsqrtf((float)(v + 1));   // +1 = self-loop
    s[tid] = v;
    __syncthreads();
    for (int off = 1; off < 1024; off <<= 1) {
        int t = (tid >= off) ? s[tid - off] : 0;
        __syncthreads();
        s[tid] += t;
        __syncthreads();
    }
    if (i < n) g_ptr[i] = s[tid] - v;
    if (tid == 1023) g_bsum[blockIdx.x] = s[tid];
}

__global__ void k_scan23(int n, int nb) {
    __shared__ int carry;
    if (threadIdx.x == 0) {
        int acc = 0;
        for (int b = 0; b < blockIdx.x; b++) acc += g_bsum[b];
        carry = acc;
        if (blockIdx.x == nb - 1) g_ptr[n] = acc + g_bsum[nb - 1];
    }
    __syncthreads();
    int i = blockIdx.x * 1024 + threadIdx.x;
    if (i < n) {
        int p = g_ptr[i] + carry;
        g_ptr[i] = p;
        g_pos[i] = p;
    }
}

__global__ void k_fill(const void* ei, const void* batch, int E, int n) {
    int e = blockIdx.x * blockDim.x + threadIdx.x;
    if (e >= E) return;
    int is64 = g_is64;
    int s = loadIdx(ei, e, is64);
    int d = loadIdx(ei, (long long)E + e, is64);
    int p = atomicAdd(&g_pos[d], 1);
    g_csrc[p] = s;
    if (e < n) {
        int g = loadIdx(batch, e, is64);
        atomicAdd(&g_gcnt[g], 1.0f);
    }
}

// ---------------- W split/transpose ----------------
__global__ void k_wsplit(const float* __restrict__ W1, const float* __restrict__ W2,
                         const float* __restrict__ W3) {
    int i = blockIdx.x * blockDim.x + threadIdx.x;
    if (i >= 3 * HDIM * 64) return;
    int l = i >> 13, r = i & 8191;
    int n = r >> 6, kp = r & 63;
    const float* W = (l == 0) ? W1 : ((l == 1) ? W2 : W3);
    float a = W[(2 * kp) * HDIM + n];
    float b = W[(2 * kp + 1) * HDIM + n];
    float ah = __bfloat162float(__float2bfloat16_rn(a));
    float bh = __bfloat162float(__float2bfloat16_rn(b));
    __nv_bfloat162 hp = __floats2bfloat162_rn(a, b);
    __nv_bfloat162 lp = __floats2bfloat162_rn(a - ah, b - bh);
    g_wth[l][n * 64 + kp] = *(uint32_t*)&hp;
    g_wtl[l][n * 64 + kp] = *(uint32_t*)&lp;
}

// ---------------- HMMA helper ----------------
__device__ __forceinline__ void mma_bf16(float* c, const uint32_t* a, uint32_t b0, uint32_t b1) {
    asm volatile("mma.sync.aligned.m16n8k16.row.col.f32.bf16.bf16.f32 "
                 "{%0,%1,%2,%3}, {%4,%5,%6,%7}, {%8,%9}, {%0,%1,%2,%3};"
                 : "+f"(c[0]), "+f"(c[1]), "+f"(c[2]), "+f"(c[3])
                 : "r"(a[0]), "r"(a[1]), "r"(a[2]), "r"(a[3]), "r"(b0), "r"(b1));
}

// smem layout (u32 units): M=64 A tile (hi/lo) + full 128-col B (hi/lo), stride 68
#define SROW 68
#define SA_HI 0
#define SA_LO (64 * SROW)
#define SB_HI (2 * 64 * SROW)
#define SB_LO (SB_HI + 128 * SROW)
#define GSMEM_BYTES ((SB_LO + 128 * SROW) * 4)

// MMA phase: C[64 x 128] = A @ B^T from split smem, write fp16 dst
__device__ __forceinline__ void mma_phase(const uint32_t* sm, __half* dst,
                                          int rowbase, int nrows, int tid) {
    int lane = tid & 31, warp = tid >> 5;
    int g = lane >> 2, tig = lane & 3;
    int m0 = (warp >> 1) * 16;
    int n0 = (warp & 1) * 64;

    float acc[8][4];
#pragma unroll
    for (int j = 0; j < 8; j++)
#pragma unroll
        for (int q = 0; q < 4; q++) acc[j][q] = 0.f;

#pragma unroll 1
    for (int s = 0; s < 8; s++) {
        int kb = s * 8;
        int o0 = (m0 + g) * SROW + kb + tig;
        int o1 = (m0 + 8 + g) * SROW + kb + tig;
        uint32_t ah[4], al[4];
        ah[0] = sm[SA_HI + o0]; ah[1] = sm[SA_HI + o1];
        ah[2] = sm[SA_HI + o0 + 4]; ah[3] = sm[SA_HI + o1 + 4];
        al[0] = sm[SA_LO + o0]; al[1] = sm[SA_LO + o1];
        al[2] = sm[SA_LO + o0 + 4]; al[3] = sm[SA_LO + o1 + 4];
#pragma unroll
        for (int j = 0; j < 8; j++) {
            int nn = n0 + j * 8 + g;
            int ob = nn * SROW + kb + tig;
            uint32_t bh0 = sm[SB_HI + ob], bh1 = sm[SB_HI + ob + 4];
            uint32_t bl0 = sm[SB_LO + ob], bl1 = sm[SB_LO + ob + 4];
            mma_bf16(acc[j], ah, bh0, bh1);
            mma_bf16(acc[j], ah, bl0, bl1);
            mma_bf16(acc[j], al, bh0, bh1);
        }
    }

#pragma unroll
    for (int j = 0; j < 8; j++) {
        int r0 = rowbase + m0 + g;
        int c = n0 + j * 8 + tig * 2;
        if (r0 < nrows) {
            __half2 h = __floats2half2_rn(acc[j][0], acc[j][1]);
            *(__half2*)&dst[(size_t)r0 * HDIM + c] = h;
        }
        if (r0 + 8 < nrows) {
            __half2 h = __floats2half2_rn(acc[j][2], acc[j][3]);
            *(__half2*)&dst[(size_t)(r0 + 8) * HDIM + c] = h;
        }
    }
}

// B copy: pre-split W^T global -> smem
__device__ __forceinline__ void b_copy(uint32_t* sm, int layer, int tid) {
    const uint32_t* wth = g_wth[layer];
    const uint32_t* wtl = g_wtl[layer];
#pragma unroll
    for (int it = 0; it < 32; it++) {
        int idx = tid + it * 256;           // 0..8191
        int n = idx >> 6, kp = idx & 63;
        sm[SB_HI + n * SROW + kp] = wth[idx];
        sm[SB_LO + n * SROW + kp] = wtl[idx];
    }
}

__device__ __forceinline__ void split2(float x, float y, uint32_t& hi, uint32_t& lo) {
    float xh = __bfloat162float(__float2bfloat16_rn(x));
    float yh = __bfloat162float(__float2bfloat16_rn(y));
    __nv_bfloat162 hp = __floats2bfloat162_rn(x, y);
    __nv_bfloat162 lp = __floats2bfloat162_rn(x - xh, y - yh);
    hi = *(uint32_t*)&hp;
    lo = *(uint32_t*)&lp;
}

// ---------------- GEMM: g_tmp(fp16) = A @ W_layer, M=64 tile, 2 CTAs/SM ----------------
__global__ __launch_bounds__(256, 2) void k_gemm(const float* __restrict__ Aext,
                                                 int layer, int nrows) {
    extern __shared__ uint32_t sm[];
    const float* A = Aext ? Aext : g_h;
    int tid = threadIdx.x;
    int rowbase = blockIdx.x * 64;

    b_copy(sm, layer, tid);
#pragma unroll
    for (int it = 0; it < 16; it++) {
        int idx = tid + it * 256;           // 0..4095
        int row = idx >> 6, kp = idx & 63;
        int r = min(rowbase + row, nrows - 1);
        float2 v = *(const float2*)&A[(size_t)r * HDIM + kp * 2];
        uint32_t hi, lo;
        split2(v.x, v.y, hi, lo);
        sm[SA_HI + row * SROW + kp] = hi;
        sm[SA_LO + row * SROW + kp] = lo;
    }
    __syncthreads();
    mma_phase(sm, g_tmp, rowbase, nrows, tid);
}

// ---------------- aggregation: g_h = relu(D^-1/2 A D^-1/2 * g_tmp + b) ----------------
__global__ __launch_bounds__(256) void k_agg(const float* __restrict__ bias, int n) {
    int warp = threadIdx.x >> 5, lane = threadIdx.x & 31;
    int node = blockIdx.x * 8 + warp;
    if (node >= n) return;
    float4 acc = make_float4(0.f, 0.f, 0.f, 0.f);
    int beg = g_ptr[node], end = g_ptr[node + 1];
#pragma unroll 4
    for (int p = beg; p < end; p++) {
        int s = g_csrc[p];
        float ds = g_dinv[s];
        uint2 raw = *(const uint2*)&g_tmp[(size_t)s * HDIM + lane * 4];
        float2 v0 = __half22float2(*(__half2*)&raw.x);
        float2 v1 = __half22float2(*(__half2*)&raw.y);
        acc.x += ds * v0.x; acc.y += ds * v0.y;
        acc.z += ds * v1.x; acc.w += ds * v1.y;
    }
    float di = g_dinv[node];
    float di2 = di * di;
    uint2 sraw = *(const uint2*)&g_tmp[(size_t)node * HDIM + lane * 4];
    float2 s0 = __half22float2(*(__half2*)&sraw.x);
    float2 s1 = __half22float2(*(__half2*)&sraw.y);
    float4 b = ((const float4*)bias)[lane];
    float4 r;
    r.x = fmaxf(di * acc.x + di2 * s0.x + b.x, 0.f);
    r.y = fmaxf(di * acc.y + di2 * s0.y + b.y, 0.f);
    r.z = fmaxf(di * acc.z + di2 * s1.x + b.z, 0.f);
    r.w = fmaxf(di * acc.w + di2 * s1.y + b.w, 0.f);
    ((float4*)g_h)[(size_t)node * 32 + lane] = r;
}

// ---------------- pooling ----------------
#define PCHUNK 64
__global__ __launch_bounds__(128) void k_pool(const void* batch, int n) {
    int f = threadIdx.x;
    int n0 = blockIdx.x * PCHUNK;
    int n1 = min(n0 + PCHUNK, n);
    if (n0 >= n) return;
    int is64 = g_is64;
    int curg = loadIdx(batch, n0, is64);
    float acc = 0.f;
    for (int i = n0; i < n1; i++) {
        int g = loadIdx(batch, i, is64);
        if (g != curg) {
            atomicAdd(&g_pool[curg * HDIM + f], acc);
            acc = 0.f; curg = g;
        }
        acc += g_h[(size_t)i * HDIM + f];
    }
    atomicAdd(&g_pool[curg * HDIM + f], acc);
}

// ---------------- classifier ----------------
__global__ void k_cls(const float* __restrict__ Wl, const float* __restrict__ bl,
                      float* __restrict__ out) {
    int g = blockIdx.x;
    int lane = threadIdx.x;
    float invc = 1.0f / fmaxf(g_gcnt[g], 1.0f);
    float acc = (lane < CDIM) ? bl[lane] : 0.f;
    for (int k = 0; k < HDIM; k++) {
        float p = g_pool[g * HDIM + k] * invc;
        if (lane < CDIM) acc += p * Wl[k * CDIM + lane];
    }
    if (lane < CDIM) out[g * CDIM + lane] = acc;
}

// ---------------- launch ----------------
extern "C" void kernel_launch(void* const* d_in, const int* in_sizes, int n_in,
                              void* d_out, int out_size) {
    const float* x  = (const float*)d_in[0];
    const float* W1 = (const float*)d_in[1];
    const float* b1 = (const float*)d_in[2];
    const float* W2 = (const float*)d_in[3];
    const float* b2 = (const float*)d_in[4];
    const float* W3 = (const float*)d_in[5];
    const float* b3 = (const float*)d_in[6];
    const float* Wl = (const float*)d_in[7];
    const float* bl = (const float*)d_in[8];
    const void*  ei = d_in[9];
    const void*  bt = d_in[10];

    int N = in_sizes[0] / HDIM;
    int E = in_sizes[9] / 2;
    int G = out_size / CDIM;

    static cudaStream_t s_side = nullptr;
    static cudaEvent_t ev_fork = nullptr, ev_join = nullptr;
    if (!s_side) {
        cudaStreamCreateWithFlags(&s_side, cudaStreamNonBlocking);
        cudaEventCreateWithFlags(&ev_fork, cudaEventDisableTiming);
        cudaEventCreateWithFlags(&ev_join, cudaEventDisableTiming);
        cudaFuncSetAttribute(k_gemm, cudaFuncAttributeMaxDynamicSharedMemorySize, GSMEM_BYTES);
    }

    int nb = (N + 1023) / 1024;
    int mma_blocks = (N + 63) / 64;
    int agg_blocks = (N + 7) / 8;

    // fork: CSR prep on side stream; W split + GEMM1 on main
    cudaEventRecord(ev_fork, 0);
    cudaStreamWaitEvent(s_side, ev_fork, 0);

    k_init<<<(N + 255) / 256, 256, 0, s_side>>>(ei, N, G);
    k_deg<<<(E + 255) / 256, 256, 0, s_side>>>(ei, E);
    k_scan1<<<nb, 1024, 0, s_side>>>(N);
    k_scan23<<<nb, 1024, 0, s_side>>>(N, nb);
    k_fill<<<(E + 255) / 256, 256, 0, s_side>>>(ei, bt, E, N);
    cudaEventRecord(ev_join, s_side);

    k_wsplit<<<(3 * HDIM * 64 + 255) / 256, 256>>>(W1, W2, W3);
    k_gemm<<<mma_blocks, 256, GSMEM_BYTES>>>(x, 0, N);

    cudaStreamWaitEvent(0, ev_join, 0);

    k_agg<<<agg_blocks, 256>>>(b1, N);
    k_gemm<<<mma_blocks, 256, GSMEM_BYTES>>>(nullptr, 1, N);
    k_agg<<<agg_blocks, 256>>>(b2, N);
    k_gemm<<<mma_blocks, 256, GSMEM_BYTES>>>(nullptr, 2, N);
    k_agg<<<agg_blocks, 256>>>(b3, N);

    k_pool<<<(N + PCHUNK - 1) / PCHUNK, 128>>>(bt, N);
    k_cls<<<G, 32>>>(Wl, bl, (float*)d_out);
}